// round 5
// baseline (speedup 1.0000x reference)
#include <cuda_runtime.h>
#include <cstdint>

#define B_   128
#define P_   168
#define HIDC 32
#define CK   6
#define L_   163          // P - CK + 1
#define HIDR 100
#define HIDS 5
#define SKIP 24
#define PT   6
#define KDIM 4032         // P * 24
#define NDIM 32256        // P * HIDC * CK
#define HW_  24
#define M_   24
#define BCH  4096         // B_ * HIDC

#define BN_   224         // GEMM N tile: 144 CTAs exactly
#define STAGE_F 12672     // (128+224)*36 floats per stage

typedef unsigned long long ull;

// ---------------- scratch (device globals; no allocation) ----------------
__device__ float d_c[B_ * NDIM];           // conv output (post-relu)
__device__ float d_c2t[L_ * BCH];          // overlap-added, t-major [t][b][ch]
__device__ float d_h1[B_ * HIDR];
__device__ float d_hs[B_ * SKIP * HIDS];

// ---------------- helpers ----------------
__device__ __forceinline__ uint32_t pkh2(float lo, float hi) {
    uint32_t r; asm("cvt.rn.f16x2.f32 %0,%1,%2;" : "=r"(r) : "f"(hi), "f"(lo)); return r;
}
__device__ __forceinline__ void mma_f16(float& c0, float& c1, float& c2, float& c3,
                                        uint32_t a0, uint32_t a1, uint32_t a2, uint32_t a3,
                                        uint32_t b0, uint32_t b1) {
    asm volatile(
        "mma.sync.aligned.m16n8k16.row.col.f32.f16.f16.f32 "
        "{%0,%1,%2,%3},{%4,%5,%6,%7},{%8,%9},{%0,%1,%2,%3};"
        : "+f"(c0), "+f"(c1), "+f"(c2), "+f"(c3)
        : "r"(a0), "r"(a1), "r"(a2), "r"(a3), "r"(b0), "r"(b1));
}
__device__ __forceinline__ ull pk2(float lo, float hi) {
    ull r; asm("mov.b64 %0,{%1,%2};" : "=l"(r) : "f"(lo), "f"(hi)); return r;
}
__device__ __forceinline__ void unpk2(ull v, float& lo, float& hi) {
    asm("mov.b64 {%0,%1},%2;" : "=f"(lo), "=f"(hi) : "l"(v));
}
__device__ __forceinline__ ull fma2_(ull a, ull b, ull c) {
    ull d; asm("fma.rn.f32x2 %0,%1,%2,%3;" : "=l"(d) : "l"(a), "l"(b), "l"(c));
    return d;
}
__device__ __forceinline__ float tanh_ap(float x) {
    float y; asm("tanh.approx.f32 %0,%1;" : "=f"(y) : "f"(x)); return y;
}
__device__ __forceinline__ float sigm_a(float x) {
    return 0.5f * tanh_ap(0.5f * x) + 0.5f;
}

// ---------------- k1: GEMM c = relu(x @ W^T + b), fp16 m16n8k16 ----------------
// BM=128, BN=224, BK=32; 8 warps (2x4), warp tile 64x56.
// fp32 in HBM/SMEM; converted to fp16 pairs at fragment load (same mantissa as tf32).
__global__ void __launch_bounds__(256, 1) k_gemm(const float* __restrict__ x,
                                                 const float* __restrict__ W,
                                                 const float* __restrict__ bias) {
    extern __shared__ float sm[];
    const int tid = threadIdx.x;
    const long n0 = (long)blockIdx.x * BN_;
    const int lane = tid & 31, warp = tid >> 5;
    const int wm = warp >> 2, wn = warp & 3;
    uint32_t smbase = (uint32_t)__cvta_generic_to_shared(sm);
    const float* gW = W + n0 * KDIM;

    float acc[4][7][4];
#pragma unroll
    for (int i = 0; i < 4; i++)
#pragma unroll
        for (int jj = 0; jj < 7; jj++)
#pragma unroll
            for (int r = 0; r < 4; r++) acc[i][jj][r] = 0.f;

    auto load_tile = [&](int kt, int s) {
        const float* a = x + kt * 32;
        const float* w = gW + kt * 32;
        uint32_t sb = smbase + s * STAGE_F * 4;
#pragma unroll
        for (int i = 0; i < 4; i++) {
            int c = tid + i * 256;
            int row = c >> 3, kq = c & 7;
            asm volatile("cp.async.ca.shared.global [%0],[%1],16;" ::
                         "r"(sb + (row * 36 + kq * 4) * 4),
                         "l"(a + (long)row * KDIM + kq * 4));
        }
#pragma unroll
        for (int i = 0; i < 7; i++) {
            int c = tid + i * 256;
            int n = c >> 3, kq = c & 7;
            asm volatile("cp.async.ca.shared.global [%0],[%1],16;" ::
                         "r"(sb + (4608 + n * 36 + kq * 4) * 4),
                         "l"(w + (long)n * KDIM + kq * 4));
        }
        asm volatile("cp.async.commit_group;");
    };

    load_tile(0, 0);
    load_tile(1, 1);

    for (int kt = 0; kt < 126; ++kt) {
        asm volatile("cp.async.wait_group 1;");
        __syncthreads();
        const float* As = sm + (kt % 3) * STAGE_F;
        const float* Ws = As + 4608;
#pragma unroll
        for (int s = 0; s < 2; ++s) {
            const int kb = s * 16 + 2 * (lane & 3);
            uint32_t af[4][4];
            uint32_t bf[7][2];
#pragma unroll
            for (int mt = 0; mt < 4; ++mt) {
                int r0 = wm * 64 + mt * 16 + (lane >> 2);
                float2 v0 = *(const float2*)(As + r0 * 36 + kb);
                float2 v1 = *(const float2*)(As + (r0 + 8) * 36 + kb);
                float2 v2 = *(const float2*)(As + r0 * 36 + kb + 8);
                float2 v3 = *(const float2*)(As + (r0 + 8) * 36 + kb + 8);
                af[mt][0] = pkh2(v0.x, v0.y); af[mt][1] = pkh2(v1.x, v1.y);
                af[mt][2] = pkh2(v2.x, v2.y); af[mt][3] = pkh2(v3.x, v3.y);
            }
#pragma unroll
            for (int nt = 0; nt < 7; ++nt) {
                int n = wn * 56 + nt * 8 + (lane >> 2);
                float2 w0 = *(const float2*)(Ws + n * 36 + kb);
                float2 w1 = *(const float2*)(Ws + n * 36 + kb + 8);
                bf[nt][0] = pkh2(w0.x, w0.y);
                bf[nt][1] = pkh2(w1.x, w1.y);
            }
#pragma unroll
            for (int mt = 0; mt < 4; ++mt)
#pragma unroll
                for (int nt = 0; nt < 7; ++nt)
                    mma_f16(acc[mt][nt][0], acc[mt][nt][1], acc[mt][nt][2], acc[mt][nt][3],
                            af[mt][0], af[mt][1], af[mt][2], af[mt][3],
                            bf[nt][0], bf[nt][1]);
        }
        __syncthreads();
        if (kt + 2 < 126) load_tile(kt + 2, (kt + 2) % 3);
        else asm volatile("cp.async.commit_group;");
    }

#pragma unroll
    for (int mt = 0; mt < 4; ++mt) {
        int row = wm * 64 + mt * 16 + (lane >> 2);
#pragma unroll
        for (int nt = 0; nt < 7; ++nt) {
            long col = n0 + wn * 56 + nt * 8 + 2 * (lane & 3);
            float b0 = bias[col], b1 = bias[col + 1];
            float2 v0 = {fmaxf(acc[mt][nt][0] + b0, 0.f), fmaxf(acc[mt][nt][1] + b1, 0.f)};
            float2 v1 = {fmaxf(acc[mt][nt][2] + b0, 0.f), fmaxf(acc[mt][nt][3] + b1, 0.f)};
            *(float2*)&d_c[(long)row * NDIM + col] = v0;
            *(float2*)&d_c[(long)(row + 8) * NDIM + col] = v1;
        }
    }
}

// ---------------- k2: overlap-add to t-major c2t ----------------
__global__ void k_overlap() {
    int bc = blockIdx.x;           // b*32 + ch
    int b = bc >> 5, ch = bc & 31;
    int t = threadIdx.x;
    if (t >= L_) return;
    const float* cb = d_c + (long)b * NDIM + ch * (CK * P_);
    float s = 0.f;
#pragma unroll
    for (int k = 0; k < CK; k++) s += cb[k * (P_ + 1) + t];
    d_c2t[t * BCH + bc] = s;
}

// ---------------- k3: GRU1 (blocks 0..127, split dots) + skip GRU ----------
// 640 threads. Thread (g = j%300, half = j/300) computes half of each dot:
//   s_part[half][g]  = [bhh_g] + Whh_g[half] . h[half]     (13 LDS.128, 26 fma2)
//   gi_part[..][half][g] = [bih_g] + Wih_g[half] . x[t+1][half]
// h_sh padded to 104 floats (last 4 zero) with zero pad weights so both
// halves run identical 13-iteration loops.
__global__ void __launch_bounds__(640, 1) k_gru(
    const float* __restrict__ g1Wih, const float* __restrict__ g1Whh,
    const float* __restrict__ g1bih, const float* __restrict__ g1bhh,
    const float* __restrict__ gsWih, const float* __restrict__ gsWhh,
    const float* __restrict__ gsbih, const float* __restrict__ gsbhh) {
    __shared__ __align__(16) float xs[L_ * HIDC];        // 5216 floats
    __shared__ __align__(16) float h_sh[104];
    __shared__ __align__(16) float s_part[2][304];
    __shared__ __align__(16) float gi_part[2][2][304];
    const int bid = blockIdx.x;
    const int j = threadIdx.x;

    if (bid < B_) {
        // ---- stage x[t][ch] for this batch row ----
        {
            uint32_t sb = (uint32_t)__cvta_generic_to_shared(xs);
            const float* src = d_c2t + bid * HIDC;
            for (int i = j; i < L_ * 8; i += 640) {
                int t = i >> 3, part = i & 7;
                asm volatile("cp.async.ca.shared.global [%0],[%1],16;" ::
                             "r"(sb + (uint32_t)(t * HIDC + part * 4) * 4),
                             "l"(src + (long)t * BCH + part * 4));
            }
            asm volatile("cp.async.commit_group;");
        }

        const int g = (j < 600) ? (j % 300) : 0;
        const int half = (j < 600) ? (j / 300) : 0;
        const bool act = (j < 600);

        // ---- half-row weights register-resident ----
        ull whh2[26], wih2[8];
        float bih_g = 0.f, bhh_g = 0.f;
        if (act) {
            const ulonglong2* pw = (const ulonglong2*)(g1Whh + g * HIDR + half * 52);
            int nq = 13 - half;   // half0: 13 (52 floats), half1: 12 (48 floats)
#pragma unroll
            for (int q = 0; q < 13; q++) {
                if (q < nq) { ulonglong2 v = pw[q]; whh2[2*q] = v.x; whh2[2*q+1] = v.y; }
                else { whh2[2*q] = pk2(0.f, 0.f); whh2[2*q+1] = pk2(0.f, 0.f); }
            }
            const ulonglong2* pi = (const ulonglong2*)(g1Wih + g * HIDC + half * 16);
#pragma unroll
            for (int q = 0; q < 4; q++) { ulonglong2 v = pi[q]; wih2[2*q] = v.x; wih2[2*q+1] = v.y; }
            if (half == 0) { bih_g = g1bih[g]; bhh_g = g1bhh[g]; }
        }
        if (j < 104) h_sh[j] = 0.f;   // pad region stays zero
        asm volatile("cp.async.wait_group 0;");
        __syncthreads();

        // ---- prologue: gi for t=0 ----
        if (act) {
            const ull* xv = (const ull*)(xs + half * 16);
            ull g0 = pk2(bih_g, 0.f), g1v = pk2(0.f, 0.f);
#pragma unroll
            for (int q = 0; q < 4; q++) {
                g0 = fma2_(xv[2*q], wih2[2*q], g0);
                g1v = fma2_(xv[2*q+1], wih2[2*q+1], g1v);
            }
            float l0, h0, l1, h1;
            unpk2(g0, l0, h0); unpk2(g1v, l1, h1);
            gi_part[0][half][g] = (l0 + h0) + (l1 + h1);
        }
        float h_reg = 0.f;
        __syncthreads();

        for (int t = 0; t < L_; ++t) {
            if (act) {
                // gi for t+1 (independent of h)
                ull g0, g1v;
                if (t + 1 < L_) {
                    const ull* xv = (const ull*)(xs + (t + 1) * HIDC + half * 16);
                    g0 = pk2(bih_g, 0.f); g1v = pk2(0.f, 0.f);
#pragma unroll
                    for (int q = 0; q < 4; q++) {
                        g0 = fma2_(xv[2*q], wih2[2*q], g0);
                        g1v = fma2_(xv[2*q+1], wih2[2*q+1], g1v);
                    }
                }
                // s half-dot (4 accumulators)
                const ull* hp = (const ull*)h_sh + half * 26;
                ull a0 = pk2(bhh_g, 0.f), a1 = pk2(0.f, 0.f);
                ull a2 = pk2(0.f, 0.f),  a3 = pk2(0.f, 0.f);
#pragma unroll
                for (int q = 0; q < 13; q++) {
                    if (q & 1) {
                        a2 = fma2_(hp[2*q], whh2[2*q], a2);
                        a3 = fma2_(hp[2*q+1], whh2[2*q+1], a3);
                    } else {
                        a0 = fma2_(hp[2*q], whh2[2*q], a0);
                        a1 = fma2_(hp[2*q+1], whh2[2*q+1], a1);
                    }
                }
                float l0, h0, l1, h1, l2, h2f, l3, h3;
                unpk2(a0, l0, h0); unpk2(a1, l1, h1);
                unpk2(a2, l2, h2f); unpk2(a3, l3, h3);
                s_part[half][g] = ((l0 + h0) + (l1 + h1)) + ((l2 + h2f) + (l3 + h3));
                if (t + 1 < L_) {
                    float gl0, gh0, gl1, gh1;
                    unpk2(g0, gl0, gh0); unpk2(g1v, gl1, gh1);
                    gi_part[(t + 1) & 1][half][g] = (gl0 + gh0) + (gl1 + gh1);
                }
            }
            __syncthreads();
            if (j < HIDR) {
                const float* gi0 = gi_part[t & 1][0];
                const float* gi1 = gi_part[t & 1][1];
                float r = sigm_a((gi0[j] + gi1[j]) + (s_part[0][j] + s_part[1][j]));
                float z = sigm_a((gi0[j+100] + gi1[j+100]) + (s_part[0][j+100] + s_part[1][j+100]));
                float n = tanh_ap((gi0[j+200] + gi1[j+200]) + r * (s_part[0][j+200] + s_part[1][j+200]));
                h_reg = z * (h_reg - n) + n;
                h_sh[j] = h_reg;
            }
            __syncthreads();
        }
        if (j < HIDR) d_h1[bid * HIDR + j] = h_reg;
    } else {
        // ---- skip GRU: 3072 sequences, one per thread, 6 steps ----
        float* ws = xs;  // reuse pool: Wih[480], Whh[75], bih[15], bhh[15]
        for (int i = j; i < 480; i += 640) ws[i] = gsWih[i];
        for (int i = j; i < 75; i += 640) ws[480 + i] = gsWhh[i];
        if (j < 15) { ws[555 + j] = gsbih[j]; ws[570 + j] = gsbhh[j]; }
        __syncthreads();
        if (j < 192) {
            int seq = (bid - B_) * 192 + j;        // = b*SKIP + sk
            int b = seq / SKIP, sk = seq % SKIP;
            float h[5] = {0.f, 0.f, 0.f, 0.f, 0.f};
            for (int pt = 0; pt < PT; ++pt) {
                const float4* xp = (const float4*)(d_c2t + (L_ - PT * SKIP + pt * SKIP + sk) * BCH + b * HIDC);
                float xv[32];
#pragma unroll
                for (int q = 0; q < 8; ++q) {
                    float4 v = xp[q];
                    xv[4*q] = v.x; xv[4*q+1] = v.y; xv[4*q+2] = v.z; xv[4*q+3] = v.w;
                }
                float gi[15], gh[15];
#pragma unroll
                for (int g2 = 0; g2 < 15; ++g2) {
                    float a = ws[555 + g2];
#pragma unroll
                    for (int i2 = 0; i2 < 32; ++i2) a += xv[i2] * ws[g2 * 32 + i2];
                    gi[g2] = a;
                    float bg = ws[570 + g2];
#pragma unroll
                    for (int i2 = 0; i2 < 5; ++i2) bg += h[i2] * ws[480 + g2 * 5 + i2];
                    gh[g2] = bg;
                }
#pragma unroll
                for (int q = 0; q < 5; ++q) {
                    float r = sigm_a(gi[q] + gh[q]);
                    float z = sigm_a(gi[5 + q] + gh[5 + q]);
                    float n = tanh_ap(gi[10 + q] + r * gh[10 + q]);
                    h[q] = z * (h[q] - n) + n;
                }
            }
#pragma unroll
            for (int q = 0; q < 5; ++q) d_hs[seq * 5 + q] = h[q];
        }
    }
}

// ---------------- k4: final linear + highway + sigmoid (exact) ----------------
__global__ void k_fin(const float* __restrict__ x,
                      const float* __restrict__ lw, const float* __restrict__ lb,
                      const float* __restrict__ hww, const float* __restrict__ hwb,
                      float* __restrict__ out) {
    int b = blockIdx.x, m = threadIdx.x;
    if (m >= M_) return;
    const float* w = lw + m * (HIDR + SKIP * HIDS);
    float a = lb[m];
    const float* h1 = d_h1 + b * HIDR;
#pragma unroll 4
    for (int i = 0; i < HIDR; ++i) a += h1[i] * w[i];
    const float* hsp = d_hs + b * (SKIP * HIDS);
#pragma unroll 4
    for (int i = 0; i < SKIP * HIDS; ++i) a += hsp[i] * w[HIDR + i];
    float z = hwb[0];
#pragma unroll
    for (int wq = 0; wq < HW_; ++wq)
        z += x[b * KDIM + (P_ - HW_ + wq) * M_ + m] * hww[wq];
    out[b * M_ + m] = 1.f / (1.f + __expf(-(a + z)));
}

// ---------------- launch ----------------
extern "C" void kernel_launch(void* const* d_in, const int* in_sizes, int n_in,
                              void* d_out, int out_size) {
    const float* x       = (const float*)d_in[0];
    const float* conv_w  = (const float*)d_in[1];
    const float* conv_b  = (const float*)d_in[2];
    const float* g1Wih   = (const float*)d_in[3];
    const float* g1Whh   = (const float*)d_in[4];
    const float* g1bih   = (const float*)d_in[5];
    const float* g1bhh   = (const float*)d_in[6];
    const float* gsWih   = (const float*)d_in[7];
    const float* gsWhh   = (const float*)d_in[8];
    const float* gsbih   = (const float*)d_in[9];
    const float* gsbhh   = (const float*)d_in[10];
    const float* lin1_w  = (const float*)d_in[11];
    const float* lin1_b  = (const float*)d_in[12];
    const float* hw_w    = (const float*)d_in[13];
    const float* hw_b    = (const float*)d_in[14];
    float* out = (float*)d_out;

    cudaFuncSetAttribute(k_gemm, cudaFuncAttributeMaxDynamicSharedMemorySize, 3 * STAGE_F * 4);

    k_gemm<<<NDIM / BN_, 256, 3 * STAGE_F * 4>>>(x, conv_w, conv_b);
    k_overlap<<<BCH, 192>>>();
    k_gru<<<B_ + 16, 640>>>(g1Wih, g1Whh, g1bih, g1bhh, gsWih, gsWhh, gsbih, gsbhh);
    k_fin<<<B_, 32>>>(x, lin1_w, lin1_b, hw_w, hw_b, out);
}

// round 6
// speedup vs baseline: 1.1384x; 1.1384x over previous
#include <cuda_runtime.h>
#include <cstdint>

#define B_   128
#define P_   168
#define HIDC 32
#define CK   6
#define L_   163          // P - CK + 1
#define HIDR 100
#define HIDS 5
#define SKIP 24
#define PT   6
#define KDIM 4032         // P * 24
#define NDIM 32256        // P * HIDC * CK
#define HW_  24
#define M_   24
#define BCH  4096         // B_ * HIDC

#define BN_   224         // GEMM N tile: 144 CTAs exactly
#define STAGE_F 12672     // (128+224)*36 floats per stage
#define GIP   304         // padded gi row

typedef unsigned long long ull;

// ---------------- scratch (device globals; no allocation) ----------------
__device__ float d_c[B_ * NDIM];           // conv output (post-relu)
__device__ float d_c2t[L_ * BCH];          // overlap-added, t-major [t][b][ch]
__device__ float d_gi[B_ * L_ * GIP];      // precomputed input projections
__device__ float d_h1[B_ * HIDR];
__device__ float d_hs[B_ * SKIP * HIDS];

// ---------------- helpers ----------------
__device__ __forceinline__ void mma_tf32(float& c0, float& c1, float& c2, float& c3,
                                         uint32_t a0, uint32_t a1, uint32_t a2, uint32_t a3,
                                         uint32_t b0, uint32_t b1) {
    asm volatile(
        "mma.sync.aligned.m16n8k8.row.col.f32.tf32.tf32.f32 "
        "{%0,%1,%2,%3},{%4,%5,%6,%7},{%8,%9},{%0,%1,%2,%3};"
        : "+f"(c0), "+f"(c1), "+f"(c2), "+f"(c3)
        : "r"(a0), "r"(a1), "r"(a2), "r"(a3), "r"(b0), "r"(b1));
}
__device__ __forceinline__ ull pk2(float lo, float hi) {
    ull r; asm("mov.b64 %0,{%1,%2};" : "=l"(r) : "f"(lo), "f"(hi)); return r;
}
__device__ __forceinline__ void unpk2(ull v, float& lo, float& hi) {
    asm("mov.b64 {%0,%1},%2;" : "=f"(lo), "=f"(hi) : "l"(v));
}
__device__ __forceinline__ ull fma2_(ull a, ull b, ull c) {
    ull d; asm("fma.rn.f32x2 %0,%1,%2,%3;" : "=l"(d) : "l"(a), "l"(b), "l"(c));
    return d;
}
__device__ __forceinline__ float tanh_ap(float x) {
    float y; asm("tanh.approx.f32 %0,%1;" : "=f"(y) : "f"(x)); return y;
}
__device__ __forceinline__ float sigm_a(float x) {
    return 0.5f * tanh_ap(0.5f * x) + 0.5f;
}

// ---------------- k1: GEMM c = relu(x @ W^T + b), tf32 (round-4 proven) ----------
__global__ void __launch_bounds__(256, 1) k_gemm(const float* __restrict__ x,
                                                 const float* __restrict__ W,
                                                 const float* __restrict__ bias) {
    extern __shared__ float sm[];
    const int tid = threadIdx.x;
    const long n0 = (long)blockIdx.x * BN_;
    const int lane = tid & 31, warp = tid >> 5;
    const int wm = warp >> 2, wn = warp & 3;
    uint32_t smbase = (uint32_t)__cvta_generic_to_shared(sm);
    const float* gW = W + n0 * KDIM;

    float acc[4][7][4];
#pragma unroll
    for (int i = 0; i < 4; i++)
#pragma unroll
        for (int jj = 0; jj < 7; jj++)
#pragma unroll
            for (int r = 0; r < 4; r++) acc[i][jj][r] = 0.f;

    auto load_tile = [&](int kt, int s) {
        const float* a = x + kt * 32;
        const float* w = gW + kt * 32;
        uint32_t sb = smbase + s * STAGE_F * 4;
#pragma unroll
        for (int i = 0; i < 4; i++) {
            int c = tid + i * 256;
            int row = c >> 3, kq = c & 7;
            asm volatile("cp.async.ca.shared.global [%0],[%1],16;" ::
                         "r"(sb + (row * 36 + kq * 4) * 4),
                         "l"(a + (long)row * KDIM + kq * 4));
        }
#pragma unroll
        for (int i = 0; i < 7; i++) {
            int c = tid + i * 256;
            int n = c >> 3, kq = c & 7;
            asm volatile("cp.async.ca.shared.global [%0],[%1],16;" ::
                         "r"(sb + (4608 + n * 36 + kq * 4) * 4),
                         "l"(w + (long)n * KDIM + kq * 4));
        }
        asm volatile("cp.async.commit_group;");
    };

    load_tile(0, 0);
    load_tile(1, 1);

    for (int kt = 0; kt < 126; ++kt) {
        asm volatile("cp.async.wait_group 1;");
        __syncthreads();
        const float* As = sm + (kt % 3) * STAGE_F;
        const float* Ws = As + 4608;
#pragma unroll
        for (int kk = 0; kk < 32; kk += 8) {
            uint32_t af[4][4];
            uint32_t bf[7][2];
#pragma unroll
            for (int mt = 0; mt < 4; ++mt) {
                int r0 = wm * 64 + mt * 16 + (lane >> 2);
                int c0 = kk + (lane & 3);
                af[mt][0] = __float_as_uint(As[r0 * 36 + c0]);
                af[mt][1] = __float_as_uint(As[(r0 + 8) * 36 + c0]);
                af[mt][2] = __float_as_uint(As[r0 * 36 + c0 + 4]);
                af[mt][3] = __float_as_uint(As[(r0 + 8) * 36 + c0 + 4]);
            }
#pragma unroll
            for (int nt = 0; nt < 7; ++nt) {
                int n = wn * 56 + nt * 8 + (lane >> 2);
                int k = kk + (lane & 3);
                bf[nt][0] = __float_as_uint(Ws[n * 36 + k]);
                bf[nt][1] = __float_as_uint(Ws[n * 36 + k + 4]);
            }
#pragma unroll
            for (int mt = 0; mt < 4; ++mt)
#pragma unroll
                for (int nt = 0; nt < 7; ++nt)
                    mma_tf32(acc[mt][nt][0], acc[mt][nt][1], acc[mt][nt][2], acc[mt][nt][3],
                             af[mt][0], af[mt][1], af[mt][2], af[mt][3],
                             bf[nt][0], bf[nt][1]);
        }
        __syncthreads();
        if (kt + 2 < 126) load_tile(kt + 2, (kt + 2) % 3);
        else asm volatile("cp.async.commit_group;");
    }

#pragma unroll
    for (int mt = 0; mt < 4; ++mt) {
        int row = wm * 64 + mt * 16 + (lane >> 2);
#pragma unroll
        for (int nt = 0; nt < 7; ++nt) {
            long col = n0 + wn * 56 + nt * 8 + 2 * (lane & 3);
            float b0 = bias[col], b1 = bias[col + 1];
            float2 v0 = {fmaxf(acc[mt][nt][0] + b0, 0.f), fmaxf(acc[mt][nt][1] + b1, 0.f)};
            float2 v1 = {fmaxf(acc[mt][nt][2] + b0, 0.f), fmaxf(acc[mt][nt][3] + b1, 0.f)};
            *(float2*)&d_c[(long)row * NDIM + col] = v0;
            *(float2*)&d_c[(long)(row + 8) * NDIM + col] = v1;
        }
    }
}

// ---------------- k2: overlap-add to t-major c2t ----------------
__global__ void k_overlap() {
    int bc = blockIdx.x;           // b*32 + ch
    int b = bc >> 5, ch = bc & 31;
    int t = threadIdx.x;
    if (t >= L_) return;
    const float* cb = d_c + (long)b * NDIM + ch * (CK * P_);
    float s = 0.f;
#pragma unroll
    for (int k = 0; k < CK; k++) s += cb[k * (P_ + 1) + t];
    d_c2t[t * BCH + bc] = s;
}

// ---------------- k2b: precompute gi[b][t][j] = bih_j + Wih_j . x[t] --------
// grid 512 = (b, tchunk of 41); 320 threads, j<300 active; Wih rows in regs.
__global__ void __launch_bounds__(320, 2) k_gi(const float* __restrict__ g1Wih,
                                               const float* __restrict__ g1bih) {
    __shared__ __align__(16) float xs2[41 * HIDC];
    const int bx = blockIdx.x;
    const int b = bx >> 2, tc = bx & 3;
    const int t0 = tc * 41;
    const int tn = (t0 + 41 <= L_) ? 41 : (L_ - t0);
    const int j = threadIdx.x;

    {
        uint32_t sb = (uint32_t)__cvta_generic_to_shared(xs2);
        const float* src = d_c2t + b * HIDC;
        for (int i = j; i < tn * 8; i += 320) {
            int t = i >> 3, part = i & 7;
            asm volatile("cp.async.ca.shared.global [%0],[%1],16;" ::
                         "r"(sb + (uint32_t)(t * HIDC + part * 4) * 4),
                         "l"(src + (long)(t0 + t) * BCH + part * 4));
        }
        asm volatile("cp.async.commit_group;");
    }

    ull wih2[16];
    float bih_j = 0.f;
    if (j < 300) {
        const ulonglong2* pi = (const ulonglong2*)(g1Wih + j * HIDC);
#pragma unroll
        for (int q = 0; q < 8; q++) { ulonglong2 v = pi[q]; wih2[2*q] = v.x; wih2[2*q+1] = v.y; }
        bih_j = g1bih[j];
    }
    asm volatile("cp.async.wait_group 0;");
    __syncthreads();

    if (j < 300) {
        float* dst = d_gi + ((size_t)b * L_ + t0) * GIP + j;
        for (int tt = 0; tt < tn; ++tt) {
            const ull* xv = (const ull*)(xs2 + tt * HIDC);
            ull g0 = pk2(bih_j, 0.f), g1v = pk2(0.f, 0.f);
#pragma unroll
            for (int q = 0; q < 8; q++) {
                g0 = fma2_(xv[2*q], wih2[2*q], g0);
                g1v = fma2_(xv[2*q+1], wih2[2*q+1], g1v);
            }
            float l0, h0, l1, h1;
            unpk2(g0, l0, h0); unpk2(g1v, l1, h1);
            dst[(size_t)tt * GIP] = (l0 + h0) + (l1 + h1);
        }
    }
}

// ---------------- k3: GRU1 (blocks 0..127) + skip GRU (blocks 128..143) ----
// Recurrent loop now only computes s = bhh + Whh.h; gi streamed from d_gi
// via cp.async double buffer (one 1216B row per step).
__global__ void __launch_bounds__(320, 1) k_gru(
    const float* __restrict__ g1Whh, const float* __restrict__ g1bhh,
    const float* __restrict__ gsWih, const float* __restrict__ gsWhh,
    const float* __restrict__ gsbih, const float* __restrict__ gsbhh) {
    __shared__ __align__(16) float h_sh[104];
    __shared__ __align__(16) float s_sh[304];
    __shared__ __align__(16) float gi_sh[2][GIP];
    __shared__ __align__(16) float ws[592];      // skip-GRU weight pool
    const int bid = blockIdx.x;
    const int j = threadIdx.x;

    if (bid < B_) {
        uint32_t gb = (uint32_t)__cvta_generic_to_shared(gi_sh);
        const float* gsrc = d_gi + (size_t)bid * L_ * GIP;

        // prologue: stage gi[0] into buf0
        if (j < 76)
            asm volatile("cp.async.ca.shared.global [%0],[%1],16;" ::
                         "r"(gb + (uint32_t)j * 16), "l"(gsrc + j * 4));
        asm volatile("cp.async.commit_group;");

        // ---- Whh rows register-resident ----
        ull whh2[50];
        float bhh_j = 0.f;
        if (j < 300) {
            const ulonglong2* pw = (const ulonglong2*)(g1Whh + j * HIDR);
#pragma unroll
            for (int q = 0; q < 25; q++) { ulonglong2 v = pw[q]; whh2[2*q] = v.x; whh2[2*q+1] = v.y; }
            bhh_j = g1bhh[j];
        }
        if (j < 104) h_sh[j] = 0.f;
        float h_reg = 0.f;
        asm volatile("cp.async.wait_group 0;");
        __syncthreads();

        for (int t = 0; t < L_; ++t) {
            // prefetch gi[t+1] into the other buffer
            if (t + 1 < L_) {
                if (j < 76)
                    asm volatile("cp.async.ca.shared.global [%0],[%1],16;" ::
                                 "r"(gb + (uint32_t)(((t + 1) & 1) * GIP + j * 4) * 4),
                                 "l"(gsrc + (size_t)(t + 1) * GIP + j * 4));
                asm volatile("cp.async.commit_group;");
            }
            if (j < 300) {
                const ulonglong2* h2 = (const ulonglong2*)h_sh;
                ull a0 = pk2(bhh_j, 0.f), a1 = pk2(0.f, 0.f);
                ull a2 = pk2(0.f, 0.f),  a3 = pk2(0.f, 0.f);
#pragma unroll
                for (int q = 0; q < 25; q++) {
                    ulonglong2 hv = h2[q];
                    if (q & 1) {
                        a2 = fma2_(hv.x, whh2[2*q], a2);
                        a3 = fma2_(hv.y, whh2[2*q+1], a3);
                    } else {
                        a0 = fma2_(hv.x, whh2[2*q], a0);
                        a1 = fma2_(hv.y, whh2[2*q+1], a1);
                    }
                }
                float l0, h0, l1, h1, l2, h2f, l3, h3;
                unpk2(a0, l0, h0); unpk2(a1, l1, h1);
                unpk2(a2, l2, h2f); unpk2(a3, l3, h3);
                s_sh[j] = ((l0 + h0) + (l1 + h1)) + ((l2 + h2f) + (l3 + h3));
            }
            if (t + 1 < L_) asm volatile("cp.async.wait_group 1;");
            else            asm volatile("cp.async.wait_group 0;");
            __syncthreads();
            if (j < HIDR) {
                const float* gi = gi_sh[t & 1];
                float r = sigm_a(gi[j] + s_sh[j]);
                float z = sigm_a(gi[j + 100] + s_sh[j + 100]);
                float n = tanh_ap(gi[j + 200] + r * s_sh[j + 200]);
                h_reg = z * (h_reg - n) + n;
                h_sh[j] = h_reg;
            }
            __syncthreads();
        }
        if (j < HIDR) d_h1[bid * HIDR + j] = h_reg;
    } else {
        // ---- skip GRU: 3072 sequences, one per thread, 6 steps ----
        for (int i = j; i < 480; i += 320) ws[i] = gsWih[i];
        for (int i = j; i < 75; i += 320) ws[480 + i] = gsWhh[i];
        if (j < 15) { ws[555 + j] = gsbih[j]; ws[570 + j] = gsbhh[j]; }
        __syncthreads();
        if (j < 192) {
            int seq = (bid - B_) * 192 + j;        // = b*SKIP + sk
            int b = seq / SKIP, sk = seq % SKIP;
            float h[5] = {0.f, 0.f, 0.f, 0.f, 0.f};
            for (int pt = 0; pt < PT; ++pt) {
                const float4* xp = (const float4*)(d_c2t + (L_ - PT * SKIP + pt * SKIP + sk) * BCH + b * HIDC);
                float xv[32];
#pragma unroll
                for (int q = 0; q < 8; ++q) {
                    float4 v = xp[q];
                    xv[4*q] = v.x; xv[4*q+1] = v.y; xv[4*q+2] = v.z; xv[4*q+3] = v.w;
                }
                float gi[15], gh[15];
#pragma unroll
                for (int g2 = 0; g2 < 15; ++g2) {
                    float a = ws[555 + g2];
#pragma unroll
                    for (int i2 = 0; i2 < 32; ++i2) a += xv[i2] * ws[g2 * 32 + i2];
                    gi[g2] = a;
                    float bg = ws[570 + g2];
#pragma unroll
                    for (int i2 = 0; i2 < 5; ++i2) bg += h[i2] * ws[480 + g2 * 5 + i2];
                    gh[g2] = bg;
                }
#pragma unroll
                for (int q = 0; q < 5; ++q) {
                    float r = sigm_a(gi[q] + gh[q]);
                    float z = sigm_a(gi[5 + q] + gh[5 + q]);
                    float n = tanh_ap(gi[10 + q] + r * gh[10 + q]);
                    h[q] = z * (h[q] - n) + n;
                }
            }
#pragma unroll
            for (int q = 0; q < 5; ++q) d_hs[seq * 5 + q] = h[q];
        }
    }
}

// ---------------- k4: final linear + highway + sigmoid; warp per output ----
__global__ void __launch_bounds__(768) k_fin(const float* __restrict__ x,
                      const float* __restrict__ lw, const float* __restrict__ lb,
                      const float* __restrict__ hww, const float* __restrict__ hwb,
                      float* __restrict__ out) {
    int b = blockIdx.x;
    int m = threadIdx.x >> 5, lane = threadIdx.x & 31;
    const float* w = lw + m * (HIDR + SKIP * HIDS);
    float a = 0.f;
#pragma unroll
    for (int q = 0; q < 8; ++q) {
        int i = lane + 32 * q;
        if (i < HIDR) a += w[i] * d_h1[b * HIDR + i];
        else if (i < 220) a += w[i] * d_hs[b * 120 + i - 100];
        else if (i < 244) a += hww[i - 220] * x[b * KDIM + (P_ - HW_ + i - 220) * M_ + m];
    }
#pragma unroll
    for (int off = 16; off > 0; off >>= 1)
        a += __shfl_xor_sync(0xffffffffu, a, off);
    if (lane == 0)
        out[b * M_ + m] = 1.f / (1.f + __expf(-(a + lb[m] + hwb[0])));
}

// ---------------- launch ----------------
extern "C" void kernel_launch(void* const* d_in, const int* in_sizes, int n_in,
                              void* d_out, int out_size) {
    const float* x       = (const float*)d_in[0];
    const float* conv_w  = (const float*)d_in[1];
    const float* conv_b  = (const float*)d_in[2];
    const float* g1Wih   = (const float*)d_in[3];
    const float* g1Whh   = (const float*)d_in[4];
    const float* g1bih   = (const float*)d_in[5];
    const float* g1bhh   = (const float*)d_in[6];
    const float* gsWih   = (const float*)d_in[7];
    const float* gsWhh   = (const float*)d_in[8];
    const float* gsbih   = (const float*)d_in[9];
    const float* gsbhh   = (const float*)d_in[10];
    const float* lin1_w  = (const float*)d_in[11];
    const float* lin1_b  = (const float*)d_in[12];
    const float* hw_w    = (const float*)d_in[13];
    const float* hw_b    = (const float*)d_in[14];
    float* out = (float*)d_out;

    cudaFuncSetAttribute(k_gemm, cudaFuncAttributeMaxDynamicSharedMemorySize, 3 * STAGE_F * 4);

    k_gemm<<<NDIM / BN_, 256, 3 * STAGE_F * 4>>>(x, conv_w, conv_b);
    k_overlap<<<BCH, 192>>>();
    k_gi<<<B_ * 4, 320>>>(g1Wih, g1bih);
    k_gru<<<B_ + 16, 320>>>(g1Whh, g1bhh, gsWih, gsWhh, gsbih, gsbhh);
    k_fin<<<B_, 768>>>(x, lin1_w, lin1_b, hw_w, hw_b, out);
}